// round 8
// baseline (speedup 1.0000x reference)
#include <cuda_runtime.h>
#include <cuda_bf16.h>
#include <cstdint>

// upfirdn2d(x, outer([1,3,3,1])*4/64, up=2, pad=(2,1))
// Per-dim: even out 2i = .75*x[i] + .25*x[i-1]; odd out 2i+1 = .75*x[i] + .25*x[i+1]
//
// One warp per 8 consecutive input rows (16 output rows = 8KB contiguous
// output stream per warp). Plain STG.128 stores (no SMEM staging).

static constexpr int H   = 64;
static constexpr int W   = 64;
static constexpr int OW  = 128;
static constexpr int RPW = 8;   // input rows per warp

__global__ __launch_bounds__(256) void upsample_fir_oct_kernel(
    const float* __restrict__ x, float* __restrict__ out)
{
    const int wid  = threadIdx.x >> 5;
    const int lane = threadIdx.x & 31;
    const int gw   = (blockIdx.x << 3) + wid;      // global warp id

    const int plane = gw >> 3;                     // 8 warps per plane (64/8)
    const int i0    = (gw & 7) * RPW;              // first input row

    const float* __restrict__ xp = x   + plane * (H * W) + 2 * lane;
    float*       __restrict__ op = out + plane * (2 * H * OW) + (i0 << 8) + 4 * lane;

    // Load RPW+2 = 10 input rows: i0-1 .. i0+8 (zero outside [0,H)).
    float2 r[RPW + 2];
    #pragma unroll
    for (int j = 0; j < RPW + 2; j++) {
        const int row = i0 - 1 + j;
        r[j] = ((unsigned)row < (unsigned)H)
                 ? *reinterpret_cast<const float2*>(xp + row * W)
                 : make_float2(0.f, 0.f);
    }

    const float W0 = 0.75f, W1 = 0.25f;
    const bool l0 = (lane == 0), l31 = (lane == 31);

    // Rolling horizontal filter (keep 3 filtered rows live) + store pairs.
    float hA[4], hB[4], hC[4];

    // h(row j) -> dst[4]
    auto hfilt = [&](int j, float* dst) {
        float prev = __shfl_up_sync(0xffffffffu, r[j].y, 1);
        float next = __shfl_down_sync(0xffffffffu, r[j].x, 1);
        if (l0)  prev = 0.f;
        if (l31) next = 0.f;
        dst[0] = W0 * r[j].x + W1 * prev;
        dst[1] = W0 * r[j].x + W1 * r[j].y;
        dst[2] = W0 * r[j].y + W1 * r[j].x;
        dst[3] = W0 * r[j].y + W1 * next;
    };

    hfilt(0, hA);
    hfilt(1, hB);

    #pragma unroll
    for (int k = 0; k < RPW; k++) {
        hfilt(k + 2, hC);

        float4 e, o;
        e.x = W0 * hB[0] + W1 * hA[0];
        e.y = W0 * hB[1] + W1 * hA[1];
        e.z = W0 * hB[2] + W1 * hA[2];
        e.w = W0 * hB[3] + W1 * hA[3];

        o.x = W0 * hB[0] + W1 * hC[0];
        o.y = W0 * hB[1] + W1 * hC[1];
        o.z = W0 * hB[2] + W1 * hC[2];
        o.w = W0 * hB[3] + W1 * hC[3];

        *reinterpret_cast<float4*>(op + (2 * k) * OW)     = e;
        *reinterpret_cast<float4*>(op + (2 * k + 1) * OW) = o;

        // roll: A <- B, B <- C
        #pragma unroll
        for (int t = 0; t < 4; t++) { hA[t] = hB[t]; hB[t] = hC[t]; }
    }
}

extern "C" void kernel_launch(void* const* d_in, const int* in_sizes, int n_in,
                              void* d_out, int out_size)
{
    const float* x = (const float*)d_in[0];
    float* out = (float*)d_out;

    // 16*256 planes, 8 warps per plane (8 input rows each).
    const int n_warps = 16 * 256 * (H / RPW);     // 32768
    const int threads = 256;                      // 8 warps/block
    const int blocks  = n_warps / (threads / 32); // 4096

    upsample_fir_oct_kernel<<<blocks, threads>>>(x, out);
}

// round 9
// speedup vs baseline: 1.0338x; 1.0338x over previous
#include <cuda_runtime.h>
#include <cuda_bf16.h>
#include <cstdint>

// upfirdn2d(x, outer([1,3,3,1])*4/64, up=2, pad=(2,1))
// Per-dim: even out 2i = .75*x[i] + .25*x[i-1]; odd out 2i+1 = .75*x[i] + .25*x[i+1]
//
// Block = 8 warps; each warp computes 4 input rows (8 output rows). The block's
// 64 output rows form ONE contiguous 32KB chunk. Stage in SMEM, emit one
// cp.async.bulk 32KB sequential store, and wait only for the SMEM READ to
// complete (wait_group.read) so the DRAM commit drains behind CTA retirement.

static constexpr int H   = 64;
static constexpr int W   = 64;
static constexpr int OW  = 128;
static constexpr int RPW = 4;                        // input rows per warp
static constexpr int TILE_FLOATS = 8 * RPW * 2 * OW; // 8192 floats = 32KB

__global__ __launch_bounds__(256) void upsample_fir_bulkr_kernel(
    const float* __restrict__ x, float* __restrict__ out)
{
    __shared__ alignas(128) float stile[TILE_FLOATS];

    const int wid  = threadIdx.x >> 5;
    const int lane = threadIdx.x & 31;
    const int gw   = (blockIdx.x << 3) + wid;      // global warp id

    const int plane = gw >> 4;                     // 16 warps per plane
    const int i0    = (gw & 15) * RPW;             // first input row

    const float* __restrict__ xp = x + plane * (H * W) + 2 * lane;
    float* __restrict__ sp = stile + wid * (2 * RPW * OW) + 4 * lane;

    // Load 6 input rows: i0-1 .. i0+4 (zero outside [0,H)).
    float2 r[RPW + 2];
    #pragma unroll
    for (int j = 0; j < RPW + 2; j++) {
        const int row = i0 - 1 + j;
        r[j] = ((unsigned)row < (unsigned)H)
                 ? *reinterpret_cast<const float2*>(xp + row * W)
                 : make_float2(0.f, 0.f);
    }

    // Cross-lane horizontal neighbors (zero at tile edges = zero padding).
    float rp[RPW + 2], rn[RPW + 2];
    #pragma unroll
    for (int j = 0; j < RPW + 2; j++) {
        rp[j] = __shfl_up_sync(0xffffffffu, r[j].y, 1);
        rn[j] = __shfl_down_sync(0xffffffffu, r[j].x, 1);
    }
    if (lane == 0) {
        #pragma unroll
        for (int j = 0; j < RPW + 2; j++) rp[j] = 0.f;
    }
    if (lane == 31) {
        #pragma unroll
        for (int j = 0; j < RPW + 2; j++) rn[j] = 0.f;
    }

    const float W0 = 0.75f, W1 = 0.25f;

    // Horizontal filter each loaded row once.
    float h[RPW + 2][4];
    #pragma unroll
    for (int j = 0; j < RPW + 2; j++) {
        h[j][0] = W0 * r[j].x + W1 * rp[j];
        h[j][1] = W0 * r[j].x + W1 * r[j].y;
        h[j][2] = W0 * r[j].y + W1 * r[j].x;
        h[j][3] = W0 * r[j].y + W1 * rn[j];
    }

    // Vertical blend + stage 8 output rows in SMEM.
    #pragma unroll
    for (int k = 0; k < RPW; k++) {
        float4 e, o;
        e.x = W0 * h[k + 1][0] + W1 * h[k][0];
        e.y = W0 * h[k + 1][1] + W1 * h[k][1];
        e.z = W0 * h[k + 1][2] + W1 * h[k][2];
        e.w = W0 * h[k + 1][3] + W1 * h[k][3];

        o.x = W0 * h[k + 1][0] + W1 * h[k + 2][0];
        o.y = W0 * h[k + 1][1] + W1 * h[k + 2][1];
        o.z = W0 * h[k + 1][2] + W1 * h[k + 2][2];
        o.w = W0 * h[k + 1][3] + W1 * h[k + 2][3];

        *reinterpret_cast<float4*>(sp + (2 * k) * OW)     = e;
        *reinterpret_cast<float4*>(sp + (2 * k + 1) * OW) = o;
    }

    __syncthreads();
    // Order generic-proxy SMEM writes before the async-proxy bulk read.
    asm volatile("fence.proxy.async.shared::cta;" ::: "memory");

    if (threadIdx.x == 0) {
        // One 32KB perfectly-sequential bulk store per block.
        float* gdst = out + (size_t)blockIdx.x * TILE_FLOATS;
        uint32_t saddr;
        asm("{ .reg .u64 t; cvta.to.shared.u64 t, %1; cvt.u32.u64 %0, t; }"
            : "=r"(saddr) : "l"(stile));
        asm volatile(
            "cp.async.bulk.global.shared::cta.bulk_group [%0], [%1], %2;"
            :: "l"(gdst), "r"(saddr), "n"((int)(TILE_FLOATS * sizeof(float)))
            : "memory");
        asm volatile("cp.async.bulk.commit_group;" ::: "memory");
        // Wait ONLY for the SMEM read to finish (CTA-local hazard); the
        // global write drains asynchronously past CTA retirement.
        asm volatile("cp.async.bulk.wait_group.read 0;" ::: "memory");
    }
}

extern "C" void kernel_launch(void* const* d_in, const int* in_sizes, int n_in,
                              void* d_out, int out_size)
{
    const float* x = (const float*)d_in[0];
    float* out = (float*)d_out;

    const int n_warps = 16 * 256 * (H / RPW);     // 65536
    const int threads = 256;
    const int blocks  = n_warps / (threads / 32); // 8192

    upsample_fir_bulkr_kernel<<<blocks, threads>>>(x, out);
}

// round 10
// speedup vs baseline: 1.0437x; 1.0096x over previous
#include <cuda_runtime.h>
#include <cuda_bf16.h>
#include <cstdint>

// upfirdn2d(x, outer([1,3,3,1])*4/64, up=2, pad=(2,1))
// Per-dim: even out 2i = .75*x[i] + .25*x[i-1]; odd out 2i+1 = .75*x[i] + .25*x[i+1]
//
// Block = 4 warps; each warp computes 4 input rows (8 output rows). The block's
// 32 output rows form ONE contiguous 16KB chunk. Stage in SMEM, emit one
// cp.async.bulk 16KB sequential store, wait only for the SMEM READ.
// 128-thread blocks: narrower barrier, 16KB smem -> ~2x CTAs/SM vs 32KB tile.

static constexpr int H   = 64;
static constexpr int W   = 64;
static constexpr int OW  = 128;
static constexpr int RPW = 4;                        // input rows per warp
static constexpr int WPB = 4;                        // warps per block
static constexpr int TILE_FLOATS = WPB * RPW * 2 * OW; // 4096 floats = 16KB

__global__ __launch_bounds__(128) void upsample_fir_bulk128_kernel(
    const float* __restrict__ x, float* __restrict__ out)
{
    __shared__ alignas(128) float stile[TILE_FLOATS];

    const int wid  = threadIdx.x >> 5;
    const int lane = threadIdx.x & 31;
    const int gw   = (blockIdx.x << 2) + wid;      // global warp id

    const int plane = gw >> 4;                     // 16 warps per plane
    const int i0    = (gw & 15) * RPW;             // first input row

    const float* __restrict__ xp = x + plane * (H * W) + 2 * lane;
    float* __restrict__ sp = stile + wid * (2 * RPW * OW) + 4 * lane;

    // Load 6 input rows: i0-1 .. i0+4 (zero outside [0,H)).
    float2 r[RPW + 2];
    #pragma unroll
    for (int j = 0; j < RPW + 2; j++) {
        const int row = i0 - 1 + j;
        r[j] = ((unsigned)row < (unsigned)H)
                 ? *reinterpret_cast<const float2*>(xp + row * W)
                 : make_float2(0.f, 0.f);
    }

    // Cross-lane horizontal neighbors (zero at tile edges = zero padding).
    float rp[RPW + 2], rn[RPW + 2];
    #pragma unroll
    for (int j = 0; j < RPW + 2; j++) {
        rp[j] = __shfl_up_sync(0xffffffffu, r[j].y, 1);
        rn[j] = __shfl_down_sync(0xffffffffu, r[j].x, 1);
    }
    if (lane == 0) {
        #pragma unroll
        for (int j = 0; j < RPW + 2; j++) rp[j] = 0.f;
    }
    if (lane == 31) {
        #pragma unroll
        for (int j = 0; j < RPW + 2; j++) rn[j] = 0.f;
    }

    const float W0 = 0.75f, W1 = 0.25f;

    // Horizontal filter each loaded row once.
    float h[RPW + 2][4];
    #pragma unroll
    for (int j = 0; j < RPW + 2; j++) {
        h[j][0] = W0 * r[j].x + W1 * rp[j];
        h[j][1] = W0 * r[j].x + W1 * r[j].y;
        h[j][2] = W0 * r[j].y + W1 * r[j].x;
        h[j][3] = W0 * r[j].y + W1 * rn[j];
    }

    // Vertical blend + stage 8 output rows in SMEM.
    #pragma unroll
    for (int k = 0; k < RPW; k++) {
        float4 e, o;
        e.x = W0 * h[k + 1][0] + W1 * h[k][0];
        e.y = W0 * h[k + 1][1] + W1 * h[k][1];
        e.z = W0 * h[k + 1][2] + W1 * h[k][2];
        e.w = W0 * h[k + 1][3] + W1 * h[k][3];

        o.x = W0 * h[k + 1][0] + W1 * h[k + 2][0];
        o.y = W0 * h[k + 1][1] + W1 * h[k + 2][1];
        o.z = W0 * h[k + 1][2] + W1 * h[k + 2][2];
        o.w = W0 * h[k + 1][3] + W1 * h[k + 2][3];

        *reinterpret_cast<float4*>(sp + (2 * k) * OW)     = e;
        *reinterpret_cast<float4*>(sp + (2 * k + 1) * OW) = o;
    }

    __syncthreads();
    // Order generic-proxy SMEM writes before the async-proxy bulk read.
    asm volatile("fence.proxy.async.shared::cta;" ::: "memory");

    if (threadIdx.x == 0) {
        // One 16KB perfectly-sequential bulk store per block.
        float* gdst = out + (size_t)blockIdx.x * TILE_FLOATS;
        uint32_t saddr;
        asm("{ .reg .u64 t; cvta.to.shared.u64 t, %1; cvt.u32.u64 %0, t; }"
            : "=r"(saddr) : "l"(stile));
        asm volatile(
            "cp.async.bulk.global.shared::cta.bulk_group [%0], [%1], %2;"
            :: "l"(gdst), "r"(saddr), "n"((int)(TILE_FLOATS * sizeof(float)))
            : "memory");
        asm volatile("cp.async.bulk.commit_group;" ::: "memory");
        // Wait ONLY for the SMEM read (CTA-local hazard); the global write
        // drains asynchronously past CTA retirement.
        asm volatile("cp.async.bulk.wait_group.read 0;" ::: "memory");
    }
}

extern "C" void kernel_launch(void* const* d_in, const int* in_sizes, int n_in,
                              void* d_out, int out_size)
{
    const float* x = (const float*)d_in[0];
    float* out = (float*)d_out;

    const int n_warps = 16 * 256 * (H / RPW);     // 65536
    const int threads = 128;                      // 4 warps/block
    const int blocks  = n_warps / (threads / 32); // 16384

    upsample_fir_bulk128_kernel<<<blocks, threads>>>(x, out);
}

// round 11
// speedup vs baseline: 1.0449x; 1.0012x over previous
#include <cuda_runtime.h>
#include <cuda_bf16.h>
#include <cstdint>

// upfirdn2d(x, outer([1,3,3,1])*4/64, up=2, pad=(2,1))
// Per-dim: even out 2i = .75*x[i] + .25*x[i-1]; odd out 2i+1 = .75*x[i] + .25*x[i+1]
//
// 128-thread blocks, one warp per 4 input rows (8 output rows = 4KB contiguous
// chunk). Each warp stages its 4KB in a private SMEM slice and issues its OWN
// cp.async.bulk sequential store. NO block-wide barrier: warps are fully
// decoupled; only wait_group.read (SMEM-read done) gates warp exit.

static constexpr int H   = 64;
static constexpr int W   = 64;
static constexpr int OW  = 128;
static constexpr int RPW = 4;                         // input rows per warp
static constexpr int WPB = 4;                         // warps per block
static constexpr int WARP_FLOATS = 2 * RPW * OW;      // 1024 floats = 4KB

__global__ __launch_bounds__(128) void upsample_fir_wbulk128_kernel(
    const float* __restrict__ x, float* __restrict__ out)
{
    __shared__ alignas(128) float stile[WPB * WARP_FLOATS];  // 16KB

    const int wid  = threadIdx.x >> 5;
    const int lane = threadIdx.x & 31;
    const int gw   = (blockIdx.x << 2) + wid;      // global warp id

    const int plane = gw >> 4;                     // 16 warps per plane
    const int i0    = (gw & 15) * RPW;             // first input row

    const float* __restrict__ xp = x + plane * (H * W) + 2 * lane;
    float* __restrict__ swarp = stile + wid * WARP_FLOATS;
    float* __restrict__ sp    = swarp + 4 * lane;

    // Load 6 input rows: i0-1 .. i0+4 (zero outside [0,H)).
    float2 r[RPW + 2];
    #pragma unroll
    for (int j = 0; j < RPW + 2; j++) {
        const int row = i0 - 1 + j;
        r[j] = ((unsigned)row < (unsigned)H)
                 ? *reinterpret_cast<const float2*>(xp + row * W)
                 : make_float2(0.f, 0.f);
    }

    // Cross-lane horizontal neighbors (zero at tile edges = zero padding).
    float rp[RPW + 2], rn[RPW + 2];
    #pragma unroll
    for (int j = 0; j < RPW + 2; j++) {
        rp[j] = __shfl_up_sync(0xffffffffu, r[j].y, 1);
        rn[j] = __shfl_down_sync(0xffffffffu, r[j].x, 1);
    }
    if (lane == 0) {
        #pragma unroll
        for (int j = 0; j < RPW + 2; j++) rp[j] = 0.f;
    }
    if (lane == 31) {
        #pragma unroll
        for (int j = 0; j < RPW + 2; j++) rn[j] = 0.f;
    }

    const float W0 = 0.75f, W1 = 0.25f;

    // Horizontal filter each loaded row once.
    float h[RPW + 2][4];
    #pragma unroll
    for (int j = 0; j < RPW + 2; j++) {
        h[j][0] = W0 * r[j].x + W1 * rp[j];
        h[j][1] = W0 * r[j].x + W1 * r[j].y;
        h[j][2] = W0 * r[j].y + W1 * r[j].x;
        h[j][3] = W0 * r[j].y + W1 * rn[j];
    }

    // Vertical blend + stage 8 output rows into this warp's SMEM slice.
    #pragma unroll
    for (int k = 0; k < RPW; k++) {
        float4 e, o;
        e.x = W0 * h[k + 1][0] + W1 * h[k][0];
        e.y = W0 * h[k + 1][1] + W1 * h[k][1];
        e.z = W0 * h[k + 1][2] + W1 * h[k][2];
        e.w = W0 * h[k + 1][3] + W1 * h[k][3];

        o.x = W0 * h[k + 1][0] + W1 * h[k + 2][0];
        o.y = W0 * h[k + 1][1] + W1 * h[k + 2][1];
        o.z = W0 * h[k + 1][2] + W1 * h[k + 2][2];
        o.w = W0 * h[k + 1][3] + W1 * h[k + 2][3];

        *reinterpret_cast<float4*>(sp + (2 * k) * OW)     = e;
        *reinterpret_cast<float4*>(sp + (2 * k + 1) * OW) = o;
    }

    __syncwarp();
    if (lane == 0) {
        // Order this warp's generic-proxy SMEM writes before the async read.
        asm volatile("fence.proxy.async.shared::cta;" ::: "memory");
        float* gdst = out + (size_t)gw * WARP_FLOATS;   // 4KB sequential chunk
        uint32_t saddr;
        asm("{ .reg .u64 t; cvta.to.shared.u64 t, %1; cvt.u32.u64 %0, t; }"
            : "=r"(saddr) : "l"(swarp));
        asm volatile(
            "cp.async.bulk.global.shared::cta.bulk_group [%0], [%1], %2;"
            :: "l"(gdst), "r"(saddr), "n"((int)(WARP_FLOATS * sizeof(float)))
            : "memory");
        asm volatile("cp.async.bulk.commit_group;" ::: "memory");
        // Wait ONLY for the SMEM read (CTA-local hazard); the global write
        // drains asynchronously past warp retirement.
        asm volatile("cp.async.bulk.wait_group.read 0;" ::: "memory");
    }
}

extern "C" void kernel_launch(void* const* d_in, const int* in_sizes, int n_in,
                              void* d_out, int out_size)
{
    const float* x = (const float*)d_in[0];
    float* out = (float*)d_out;

    const int n_warps = 16 * 256 * (H / RPW);     // 65536
    const int threads = 128;                      // 4 warps/block
    const int blocks  = n_warps / (threads / 32); // 16384

    upsample_fir_wbulk128_kernel<<<blocks, threads>>>(x, out);
}